// round 7
// baseline (speedup 1.0000x reference)
#include <cuda_runtime.h>
#include <cuda_bf16.h>
#include <cuda_fp16.h>
#include <cstdint>

#define N_NODES 50000
#define D 128
#define TM 32
#define SCAN_BS 1024
#define SCAN_NB ((N_NODES + SCAN_BS - 1) / SCAN_BS)   // 49
#define P2 264   // padded row stride (bf16 elems) for K=256 tiles
#define P1 136   // padded row stride for K=128 tiles

// ---- scratch (allocation-free: __device__ globals) ----
__device__ float   g_agg[(size_t)N_NODES * D];   // mean-aggregated features (fp32)
__device__ float   g_h1 [(size_t)N_NODES * D];
__device__ float   g_h2 [(size_t)N_NODES * D];
__device__ __half2 g_xh [(size_t)N_NODES * (D / 2)];  // fp16 copy of x (gather src)
__device__ __half2 g_h1h[(size_t)N_NODES * (D / 2)];  // fp16 copy of h1 (gather src)
__device__ float   g_inv[N_NODES];
__device__ int     g_cnt[N_NODES];
__device__ int     g_scan[N_NODES];
__device__ int     g_rowptr[N_NODES + 1];
__device__ int     g_cursor[N_NODES];
__device__ int     g_eidx[1700000];              // src node per CSR slot (E <= 1.6M)
__device__ int     g_bsum[SCAN_NB];
__device__ int     g_boff[SCAN_NB];

// ================= CSR build =================
__global__ void k_zero_cnt() {
    int i = blockIdx.x * blockDim.x + threadIdx.x;
    if (i < N_NODES) g_cnt[i] = 0;
}

// edge_index is int32 on device: layout [2, E] row-major.
__global__ void k_count(const int* __restrict__ ei, int E) {
    int e = blockIdx.x * blockDim.x + threadIdx.x;
    if (e < E) atomicAdd(&g_cnt[ei[E + e]], 1);
}

__global__ void k_scan1() {
    __shared__ int sh[SCAN_BS];
    int i = blockIdx.x * SCAN_BS + threadIdx.x;
    int v = (i < N_NODES) ? g_cnt[i] : 0;
    sh[threadIdx.x] = v;
    __syncthreads();
    for (int off = 1; off < SCAN_BS; off <<= 1) {
        int t = (threadIdx.x >= off) ? sh[threadIdx.x - off] : 0;
        __syncthreads();
        sh[threadIdx.x] += t;
        __syncthreads();
    }
    if (i < N_NODES) g_scan[i] = sh[threadIdx.x];
    if (threadIdx.x == SCAN_BS - 1) g_bsum[blockIdx.x] = sh[threadIdx.x];
}

__global__ void k_scan2() {
    __shared__ int sh[64];
    int v = (threadIdx.x < SCAN_NB) ? g_bsum[threadIdx.x] : 0;
    sh[threadIdx.x] = v;
    __syncthreads();
    for (int off = 1; off < 64; off <<= 1) {
        int t = (threadIdx.x >= off) ? sh[threadIdx.x - off] : 0;
        __syncthreads();
        sh[threadIdx.x] += t;
        __syncthreads();
    }
    if (threadIdx.x < SCAN_NB) g_boff[threadIdx.x] = sh[threadIdx.x] - v;  // exclusive
}

__global__ void k_scan3() {
    int i = blockIdx.x * blockDim.x + threadIdx.x;
    if (i < N_NODES) {
        int incl = g_scan[i] + g_boff[i / SCAN_BS];
        int cnt  = g_cnt[i];
        int excl = incl - cnt;
        g_rowptr[i] = excl;
        g_cursor[i] = excl;
        g_inv[i]    = 1.0f / fmaxf((float)cnt, 1.0f);
        if (i == N_NODES - 1) g_rowptr[N_NODES] = incl;
    }
}

__global__ void k_fill(const int* __restrict__ ei, int E) {
    int e = blockIdx.x * blockDim.x + threadIdx.x;
    if (e < E) {
        int src = ei[e];
        int dst = ei[E + e];
        int pos = atomicAdd(&g_cursor[dst], 1);
        g_eidx[pos] = src;
    }
}

// ================= fp16 conversion of x =================
__global__ void k_cvt_x(const float* __restrict__ x) {
    size_t n = (size_t)N_NODES * (D / 2);
    for (size_t i = (size_t)blockIdx.x * blockDim.x + threadIdx.x; i < n;
         i += (size_t)gridDim.x * blockDim.x) {
        float2 v = ((const float2*)x)[i];
        g_xh[i] = __floats2half2_rn(v.x, v.y);
    }
}

// ================= gather-mean (fp16 reads, fp32 accumulate) =================
// warp per node; lane owns 4 contiguous elems of the 128-dim row (8B fp16).
__global__ __launch_bounds__(256)
void k_gather_h(int layer) {
    const __half2* feat = (layer == 0) ? g_xh : g_h1h;
    int lane = threadIdx.x & 31;
    int node = blockIdx.x * 8 + (threadIdx.x >> 5);
    if (node >= N_NODES) return;

    int b = g_rowptr[node];
    int e = g_rowptr[node + 1];
    float2 a0 = make_float2(0.f, 0.f);
    float2 a1 = make_float2(0.f, 0.f);

    int j = b;
    for (; j + 8 <= e; j += 8) {
        uint2 raw[8];
        #pragma unroll
        for (int u = 0; u < 8; u++) {
            int s = g_eidx[j + u];
            raw[u] = __ldg((const uint2*)(feat + (size_t)s * (D / 2)) + lane);
        }
        #pragma unroll
        for (int u = 0; u < 8; u++) {
            float2 f0 = __half22float2(*(__half2*)&raw[u].x);
            float2 f1 = __half22float2(*(__half2*)&raw[u].y);
            a0.x += f0.x; a0.y += f0.y;
            a1.x += f1.x; a1.y += f1.y;
        }
    }
    for (; j < e; j++) {
        int s = g_eidx[j];
        uint2 r = __ldg((const uint2*)(feat + (size_t)s * (D / 2)) + lane);
        float2 f0 = __half22float2(*(__half2*)&r.x);
        float2 f1 = __half22float2(*(__half2*)&r.y);
        a0.x += f0.x; a0.y += f0.y;
        a1.x += f1.x; a1.y += f1.y;
    }
    float sc = g_inv[node];
    float4 o = make_float4(a0.x * sc, a0.y * sc, a1.x * sc, a1.y * sc);
    ((float4*)(g_agg + (size_t)node * D))[lane] = o;
}

// ---- bf16 split helpers ----
__device__ __forceinline__ void bf16_split(float v, __nv_bfloat16& h, __nv_bfloat16& l) {
    h = __float2bfloat16(v);
    l = __float2bfloat16(v - __bfloat162float(h));
}

#define MMA_BF16(C, A0, A1, A2, A3, B0, B1)                                    \
    asm volatile(                                                              \
        "mma.sync.aligned.m16n8k16.row.col.f32.bf16.bf16.f32 "                 \
        "{%0,%1,%2,%3}, {%4,%5,%6,%7}, {%8,%9}, {%0,%1,%2,%3};"                \
        : "+f"((C)[0]), "+f"((C)[1]), "+f"((C)[2]), "+f"((C)[3])               \
        : "r"(A0), "r"(A1), "r"(A2), "r"(A3), "r"(B0), "r"(B1))

// ================= fused SAGE layer (tensor core, bf16 3-term split) =========
// out = relu( [agg|xroot](50000x256) @ [wl;wr]^T + bl )
// layer==0: xroot = x, out = g_h1 (+ fp16 shadow g_h1h); layer==1: xroot = g_h1, out = g_h2
__global__ __launch_bounds__(256, 1)
void k_sage_mma(const float* __restrict__ xext,
                const float* __restrict__ wl, const float* __restrict__ bl,
                const float* __restrict__ wr, int layer) {
    extern __shared__ __nv_bfloat16 sm[];
    __nv_bfloat16* sB_hi = sm;                       // 128 * P2
    __nv_bfloat16* sB_lo = sB_hi + 128 * P2;
    __nv_bfloat16* sA_hi = sB_lo + 128 * P2;         // 32 * P2
    __nv_bfloat16* sA_lo = sA_hi + 32 * P2;

    const float* xroot = (layer == 0) ? xext : g_h1;
    float* out = (layer == 0) ? g_h1 : g_h2;

    const int tid  = threadIdx.x;
    const int lane = tid & 31;
    const int w    = tid >> 5;
    const int g    = lane >> 2;
    const int q    = lane & 3;
    const int mr   = (w & 1) * 16;     // warp row offset within 32-row tile
    const int n0   = (w >> 1) * 32;    // warp col offset (4 n8-tiles)

    // stage weights (hi/lo split), B[n][k] with K=256 = [wl | wr]
    for (int idx = tid; idx < 128 * 256; idx += 256) {
        int n = idx >> 8, k = idx & 255;
        float v = (k < 128) ? wl[n * 128 + k] : wr[n * 128 + (k - 128)];
        __nv_bfloat16 h, l; bf16_split(v, h, l);
        sB_hi[n * P2 + k] = h;
        sB_lo[n * P2 + k] = l;
    }
    float2 bias_t[4];
    #pragma unroll
    for (int t = 0; t < 4; t++)
        bias_t[t] = *(const float2*)&bl[n0 + t * 8 + q * 2];
    __syncthreads();

    const int ntiles = (N_NODES + TM - 1) / TM;
    for (int tile = blockIdx.x; tile < ntiles; tile += gridDim.x) {
        const int row0 = tile * TM;
        __syncthreads();
        // stage A tile (32 x 256): [agg | xroot], hi/lo split
        for (int idx = tid; idx < TM * 256; idx += 256) {
            int r = idx >> 8, k = idx & 255;
            int grow = row0 + r;
            float v = 0.f;
            if (grow < N_NODES)
                v = (k < 128) ? g_agg[(size_t)grow * D + k]
                              : __ldg(&xroot[(size_t)grow * D + (k - 128)]);
            __nv_bfloat16 h, l; bf16_split(v, h, l);
            sA_hi[r * P2 + k] = h;
            sA_lo[r * P2 + k] = l;
        }
        __syncthreads();

        float acc[4][4];
        #pragma unroll
        for (int t = 0; t < 4; t++)
            #pragma unroll
            for (int c = 0; c < 4; c++) acc[t][c] = 0.f;

        #pragma unroll 4
        for (int ks = 0; ks < 16; ks++) {
            const int kk = ks * 16 + q * 2;
            const int ra = (mr + g) * P2;
            uint32_t ah0 = *(const uint32_t*)&sA_hi[ra + kk];
            uint32_t ah1 = *(const uint32_t*)&sA_hi[ra + 8 * P2 + kk];
            uint32_t ah2 = *(const uint32_t*)&sA_hi[ra + kk + 8];
            uint32_t ah3 = *(const uint32_t*)&sA_hi[ra + 8 * P2 + kk + 8];
            uint32_t al0 = *(const uint32_t*)&sA_lo[ra + kk];
            uint32_t al1 = *(const uint32_t*)&sA_lo[ra + 8 * P2 + kk];
            uint32_t al2 = *(const uint32_t*)&sA_lo[ra + kk + 8];
            uint32_t al3 = *(const uint32_t*)&sA_lo[ra + 8 * P2 + kk + 8];
            #pragma unroll
            for (int t = 0; t < 4; t++) {
                const int nb = (n0 + t * 8 + g) * P2;
                uint32_t bh0 = *(const uint32_t*)&sB_hi[nb + kk];
                uint32_t bh1 = *(const uint32_t*)&sB_hi[nb + kk + 8];
                uint32_t bl0_ = *(const uint32_t*)&sB_lo[nb + kk];
                uint32_t bl1_ = *(const uint32_t*)&sB_lo[nb + kk + 8];
                MMA_BF16(acc[t], ah0, ah1, ah2, ah3, bh0, bh1);
                MMA_BF16(acc[t], ah0, ah1, ah2, ah3, bl0_, bl1_);
                MMA_BF16(acc[t], al0, al1, al2, al3, bh0, bh1);
            }
        }

        // epilogue: bias + relu, f32 store (+ fp16 shadow for layer-2 gather)
        const int rA = row0 + mr + g;
        const int rB = rA + 8;
        #pragma unroll
        for (int t = 0; t < 4; t++) {
            const int col0 = n0 + t * 8 + q * 2;
            if (rA < N_NODES) {
                float2 o;
                o.x = fmaxf(acc[t][0] + bias_t[t].x, 0.f);
                o.y = fmaxf(acc[t][1] + bias_t[t].y, 0.f);
                *(float2*)&out[(size_t)rA * D + col0] = o;
                if (layer == 0)
                    g_h1h[(size_t)rA * (D / 2) + (col0 >> 1)] = __floats2half2_rn(o.x, o.y);
            }
            if (rB < N_NODES) {
                float2 o;
                o.x = fmaxf(acc[t][2] + bias_t[t].x, 0.f);
                o.y = fmaxf(acc[t][3] + bias_t[t].y, 0.f);
                *(float2*)&out[(size_t)rB * D + col0] = o;
                if (layer == 0)
                    g_h1h[(size_t)rB * (D / 2) + (col0 >> 1)] = __floats2half2_rn(o.x, o.y);
            }
        }
    }
}

// ================= fused MLP head (tensor core) =================
// h3 = relu(g_h2 @ mw1^T + mb1);  out = h3 @ mw2^T + mb2   -> [N]
__global__ __launch_bounds__(256, 2)
void k_mlp_mma(const float* __restrict__ mw1, const float* __restrict__ mb1,
               const float* __restrict__ mw2, const float* __restrict__ mb2,
               float* __restrict__ out) {
    extern __shared__ __nv_bfloat16 sm[];
    __nv_bfloat16* sB_hi = sm;                       // 128 * P1
    __nv_bfloat16* sB_lo = sB_hi + 128 * P1;
    __nv_bfloat16* sA_hi = sB_lo + 128 * P1;         // 32 * P1
    __nv_bfloat16* sA_lo = sA_hi + 32 * P1;
    float* s_part = (float*)(sA_lo + 32 * P1);       // [4][32]

    const int tid  = threadIdx.x;
    const int lane = tid & 31;
    const int w    = tid >> 5;
    const int g    = lane >> 2;
    const int q    = lane & 3;
    const int mr   = (w & 1) * 16;
    const int n0   = (w >> 1) * 32;
    const int grp  = w >> 1;

    for (int idx = tid; idx < 128 * 128; idx += 256) {
        int n = idx >> 7, k = idx & 127;
        __nv_bfloat16 h, l; bf16_split(mw1[idx], h, l);
        sB_hi[n * P1 + k] = h;
        sB_lo[n * P1 + k] = l;
    }
    float2 b1_t[4], w2_t[4];
    #pragma unroll
    for (int t = 0; t < 4; t++) {
        b1_t[t] = *(const float2*)&mb1[n0 + t * 8 + q * 2];
        w2_t[t] = *(const float2*)&mw2[n0 + t * 8 + q * 2];
    }
    const float b2 = mb2[0];
    __syncthreads();

    const int ntiles = (N_NODES + TM - 1) / TM;
    for (int tile = blockIdx.x; tile < ntiles; tile += gridDim.x) {
        const int row0 = tile * TM;
        __syncthreads();
        for (int idx = tid; idx < TM * 128; idx += 256) {
            int r = idx >> 7, k = idx & 127;
            int grow = row0 + r;
            float v = (grow < N_NODES) ? g_h2[(size_t)grow * D + k] : 0.f;
            __nv_bfloat16 h, l; bf16_split(v, h, l);
            sA_hi[r * P1 + k] = h;
            sA_lo[r * P1 + k] = l;
        }
        __syncthreads();

        float acc[4][4];
        #pragma unroll
        for (int t = 0; t < 4; t++)
            #pragma unroll
            for (int c = 0; c < 4; c++) acc[t][c] = 0.f;

        #pragma unroll 4
        for (int ks = 0; ks < 8; ks++) {
            const int kk = ks * 16 + q * 2;
            const int ra = (mr + g) * P1;
            uint32_t ah0 = *(const uint32_t*)&sA_hi[ra + kk];
            uint32_t ah1 = *(const uint32_t*)&sA_hi[ra + 8 * P1 + kk];
            uint32_t ah2 = *(const uint32_t*)&sA_hi[ra + kk + 8];
            uint32_t ah3 = *(const uint32_t*)&sA_hi[ra + 8 * P1 + kk + 8];
            uint32_t al0 = *(const uint32_t*)&sA_lo[ra + kk];
            uint32_t al1 = *(const uint32_t*)&sA_lo[ra + 8 * P1 + kk];
            uint32_t al2 = *(const uint32_t*)&sA_lo[ra + kk + 8];
            uint32_t al3 = *(const uint32_t*)&sA_lo[ra + 8 * P1 + kk + 8];
            #pragma unroll
            for (int t = 0; t < 4; t++) {
                const int nb = (n0 + t * 8 + g) * P1;
                uint32_t bh0 = *(const uint32_t*)&sB_hi[nb + kk];
                uint32_t bh1 = *(const uint32_t*)&sB_hi[nb + kk + 8];
                uint32_t bl0_ = *(const uint32_t*)&sB_lo[nb + kk];
                uint32_t bl1_ = *(const uint32_t*)&sB_lo[nb + kk + 8];
                MMA_BF16(acc[t], ah0, ah1, ah2, ah3, bh0, bh1);
                MMA_BF16(acc[t], ah0, ah1, ah2, ah3, bl0_, bl1_);
                MMA_BF16(acc[t], al0, al1, al2, al3, bh0, bh1);
            }
        }

        // head: relu then dot with mw2 over this warp's 32 cols
        float pg = 0.f, pg8 = 0.f;
        #pragma unroll
        for (int t = 0; t < 4; t++) {
            pg  += fmaxf(acc[t][0] + b1_t[t].x, 0.f) * w2_t[t].x
                 + fmaxf(acc[t][1] + b1_t[t].y, 0.f) * w2_t[t].y;
            pg8 += fmaxf(acc[t][2] + b1_t[t].x, 0.f) * w2_t[t].x
                 + fmaxf(acc[t][3] + b1_t[t].y, 0.f) * w2_t[t].y;
        }
        pg  += __shfl_xor_sync(0xffffffffu, pg, 1);
        pg  += __shfl_xor_sync(0xffffffffu, pg, 2);
        pg8 += __shfl_xor_sync(0xffffffffu, pg8, 1);
        pg8 += __shfl_xor_sync(0xffffffffu, pg8, 2);
        if (q == 0) {
            s_part[grp * 32 + mr + g]     = pg;
            s_part[grp * 32 + mr + g + 8] = pg8;
        }
        __syncthreads();
        if (tid < 32) {
            int grow = row0 + tid;
            if (grow < N_NODES) {
                out[grow] = s_part[tid] + s_part[32 + tid] + s_part[64 + tid]
                          + s_part[96 + tid] + b2;
            }
        }
    }
}

extern "C" void kernel_launch(void* const* d_in, const int* in_sizes, int n_in,
                              void* d_out, int out_size) {
    const float* x   = (const float*)d_in[0];
    const int*   ei  = (const int*)d_in[1];      // int32 (JAX x64 disabled)
    const float* w1l = (const float*)d_in[2];
    const float* b1l = (const float*)d_in[3];
    const float* w1r = (const float*)d_in[4];
    const float* w2l = (const float*)d_in[5];
    const float* b2l = (const float*)d_in[6];
    const float* w2r = (const float*)d_in[7];
    const float* mw1 = (const float*)d_in[8];
    const float* mb1 = (const float*)d_in[9];
    const float* mw2 = (const float*)d_in[10];
    const float* mb2 = (const float*)d_in[11];
    float* out = (float*)d_out;
    const int E = in_sizes[1] / 2;

    const int sage_smem = (2 * 128 * P2 + 2 * 32 * P2) * (int)sizeof(__nv_bfloat16); // 168960
    const int mlp_smem  = (2 * 128 * P1 + 2 * 32 * P1) * (int)sizeof(__nv_bfloat16)
                        + 4 * 32 * (int)sizeof(float);                               // 87552
    cudaFuncSetAttribute(k_sage_mma, cudaFuncAttributeMaxDynamicSharedMemorySize, sage_smem);
    cudaFuncSetAttribute(k_mlp_mma,  cudaFuncAttributeMaxDynamicSharedMemorySize, mlp_smem);

    // ---- CSR build + fp16 copy of x ----
    k_zero_cnt<<<(N_NODES + 255) / 256, 256>>>();
    k_count<<<(E + 255) / 256, 256>>>(ei, E);
    k_scan1<<<SCAN_NB, SCAN_BS>>>();
    k_scan2<<<1, 64>>>();
    k_scan3<<<(N_NODES + 255) / 256, 256>>>();
    k_fill<<<(E + 255) / 256, 256>>>(ei, E);
    k_cvt_x<<<592, 256>>>(x);

    const int gat_blocks = (N_NODES + 7) / 8;

    // ---- layer 1 ----
    k_gather_h<<<gat_blocks, 256>>>(0);
    k_sage_mma<<<148, 256, sage_smem>>>(x, w1l, b1l, w1r, 0);

    // ---- layer 2 ----
    k_gather_h<<<gat_blocks, 256>>>(1);
    k_sage_mma<<<148, 256, sage_smem>>>(x, w2l, b2l, w2r, 1);

    // ---- MLP head ----
    k_mlp_mma<<<296, 256, mlp_smem>>>(mw1, mb1, mw2, mb2, out);
}

// round 8
// speedup vs baseline: 1.9066x; 1.9066x over previous
#include <cuda_runtime.h>
#include <cuda_bf16.h>
#include <cstdint>

#define N_NODES 50000
#define D 128
#define TM 32
#define SCAN_BS 1024
#define SCAN_NB ((N_NODES + SCAN_BS - 1) / SCAN_BS)   // 49
#define P2 264   // padded row stride (bf16 elems) for K=256 tiles
#define P1 136   // padded row stride for K=128 tiles

// ---- scratch (allocation-free: __device__ globals) ----
__device__ float g_agg[(size_t)N_NODES * D];   // mean-aggregated features
__device__ float g_h1 [(size_t)N_NODES * D];
__device__ float g_h2 [(size_t)N_NODES * D];
__device__ float g_inv[N_NODES];
__device__ int   g_cnt[N_NODES];
__device__ int   g_scan[N_NODES];
__device__ int   g_rowptr[N_NODES + 1];
__device__ int   g_cursor[N_NODES];
__device__ int   g_eidx[1700000];              // src node per CSR slot (E <= 1.6M)
__device__ int   g_bsum[SCAN_NB];
__device__ int   g_boff[SCAN_NB];

// ================= CSR build =================
__global__ void k_zero_cnt() {
    int i = blockIdx.x * blockDim.x + threadIdx.x;
    if (i < N_NODES) g_cnt[i] = 0;
}

// edge_index is int32 on device: layout [2, E] row-major.
__global__ void k_count(const int* __restrict__ ei, int E) {
    int e = blockIdx.x * blockDim.x + threadIdx.x;
    if (e < E) atomicAdd(&g_cnt[ei[E + e]], 1);
}

__global__ void k_scan1() {
    __shared__ int sh[SCAN_BS];
    int i = blockIdx.x * SCAN_BS + threadIdx.x;
    int v = (i < N_NODES) ? g_cnt[i] : 0;
    sh[threadIdx.x] = v;
    __syncthreads();
    for (int off = 1; off < SCAN_BS; off <<= 1) {
        int t = (threadIdx.x >= off) ? sh[threadIdx.x - off] : 0;
        __syncthreads();
        sh[threadIdx.x] += t;
        __syncthreads();
    }
    if (i < N_NODES) g_scan[i] = sh[threadIdx.x];
    if (threadIdx.x == SCAN_BS - 1) g_bsum[blockIdx.x] = sh[threadIdx.x];
}

__global__ void k_scan2() {
    __shared__ int sh[64];
    int v = (threadIdx.x < SCAN_NB) ? g_bsum[threadIdx.x] : 0;
    sh[threadIdx.x] = v;
    __syncthreads();
    for (int off = 1; off < 64; off <<= 1) {
        int t = (threadIdx.x >= off) ? sh[threadIdx.x - off] : 0;
        __syncthreads();
        sh[threadIdx.x] += t;
        __syncthreads();
    }
    if (threadIdx.x < SCAN_NB) g_boff[threadIdx.x] = sh[threadIdx.x] - v;  // exclusive
}

__global__ void k_scan3() {
    int i = blockIdx.x * blockDim.x + threadIdx.x;
    if (i < N_NODES) {
        int incl = g_scan[i] + g_boff[i / SCAN_BS];
        int cnt  = g_cnt[i];
        int excl = incl - cnt;
        g_rowptr[i] = excl;
        g_cursor[i] = excl;
        g_inv[i]    = 1.0f / fmaxf((float)cnt, 1.0f);
        if (i == N_NODES - 1) g_rowptr[N_NODES] = incl;
    }
}

__global__ void k_fill(const int* __restrict__ ei, int E) {
    int e = blockIdx.x * blockDim.x + threadIdx.x;
    if (e < E) {
        int src = ei[e];
        int dst = ei[E + e];
        int pos = atomicAdd(&g_cursor[dst], 1);
        g_eidx[pos] = src;
    }
}

// ================= gather-mean (no atomics, fp32 — known good) =================
__global__ __launch_bounds__(256)
void k_gather(const float* __restrict__ xext, int layer) {
    const float* feat = (layer == 0) ? xext : g_h1;
    int lane = threadIdx.x & 31;
    int node = blockIdx.x * 8 + (threadIdx.x >> 5);
    if (node >= N_NODES) return;

    int b = g_rowptr[node];
    int e = g_rowptr[node + 1];
    float4 acc = make_float4(0.f, 0.f, 0.f, 0.f);

    int j = b;
    for (; j + 4 <= e; j += 4) {
        int s0 = g_eidx[j + 0], s1 = g_eidx[j + 1];
        int s2 = g_eidx[j + 2], s3 = g_eidx[j + 3];
        float4 v0 = __ldg((const float4*)(feat + (size_t)s0 * D) + lane);
        float4 v1 = __ldg((const float4*)(feat + (size_t)s1 * D) + lane);
        float4 v2 = __ldg((const float4*)(feat + (size_t)s2 * D) + lane);
        float4 v3 = __ldg((const float4*)(feat + (size_t)s3 * D) + lane);
        acc.x += (v0.x + v1.x) + (v2.x + v3.x);
        acc.y += (v0.y + v1.y) + (v2.y + v3.y);
        acc.z += (v0.z + v1.z) + (v2.z + v3.z);
        acc.w += (v0.w + v1.w) + (v2.w + v3.w);
    }
    for (; j < e; j++) {
        int s = g_eidx[j];
        float4 v = __ldg((const float4*)(feat + (size_t)s * D) + lane);
        acc.x += v.x; acc.y += v.y; acc.z += v.z; acc.w += v.w;
    }
    float sc = g_inv[node];
    acc.x *= sc; acc.y *= sc; acc.z *= sc; acc.w *= sc;
    ((float4*)(g_agg + (size_t)node * D))[lane] = acc;
}

// ---- fast packed bf16 hi/lo split of a float4, 8B smem stores ----
__device__ __forceinline__ void split4_store(__nv_bfloat16* hi_base,
                                             __nv_bfloat16* lo_base,
                                             int off, float4 v) {
    uint32_t h01, h23, l01, l23;
    asm("cvt.rn.bf16x2.f32 %0, %1, %2;" : "=r"(h01) : "f"(v.y), "f"(v.x));
    asm("cvt.rn.bf16x2.f32 %0, %1, %2;" : "=r"(h23) : "f"(v.w), "f"(v.z));
    float hx = __uint_as_float(h01 << 16);
    float hy = __uint_as_float(h01 & 0xffff0000u);
    float hz = __uint_as_float(h23 << 16);
    float hw = __uint_as_float(h23 & 0xffff0000u);
    asm("cvt.rn.bf16x2.f32 %0, %1, %2;" : "=r"(l01) : "f"(v.y - hy), "f"(v.x - hx));
    asm("cvt.rn.bf16x2.f32 %0, %1, %2;" : "=r"(l23) : "f"(v.w - hw), "f"(v.z - hz));
    *(uint2*)(hi_base + off) = make_uint2(h01, h23);
    *(uint2*)(lo_base + off) = make_uint2(l01, l23);
}

#define MMA_BF16(C, A0, A1, A2, A3, B0, B1)                                    \
    asm volatile(                                                              \
        "mma.sync.aligned.m16n8k16.row.col.f32.bf16.bf16.f32 "                 \
        "{%0,%1,%2,%3}, {%4,%5,%6,%7}, {%8,%9}, {%0,%1,%2,%3};"                \
        : "+f"((C)[0]), "+f"((C)[1]), "+f"((C)[2]), "+f"((C)[3])               \
        : "r"(A0), "r"(A1), "r"(A2), "r"(A3), "r"(B0), "r"(B1))

// ================= fused SAGE layer (tensor core, bf16 3-term split) =========
// out = relu( [agg|xroot](50000x256) @ [wl;wr]^T + bl )
__global__ __launch_bounds__(256, 1)
void k_sage_mma(const float* __restrict__ xext,
                const float* __restrict__ wl, const float* __restrict__ bl,
                const float* __restrict__ wr, int layer) {
    extern __shared__ __nv_bfloat16 sm[];
    __nv_bfloat16* sB_hi = sm;                       // 128 * P2
    __nv_bfloat16* sB_lo = sB_hi + 128 * P2;
    __nv_bfloat16* sA_hi = sB_lo + 128 * P2;         // 32 * P2
    __nv_bfloat16* sA_lo = sA_hi + 32 * P2;

    const float* xroot = (layer == 0) ? xext : g_h1;
    float* out = (layer == 0) ? g_h1 : g_h2;

    const int tid  = threadIdx.x;
    const int lane = tid & 31;
    const int w    = tid >> 5;
    const int g    = lane >> 2;
    const int q    = lane & 3;
    const int mr   = (w & 1) * 16;     // warp row offset within 32-row tile
    const int n0   = (w >> 1) * 32;    // warp col offset (4 n8-tiles)

    // stage weights (hi/lo split): B[n][k], K=256 = [wl | wr], float4 path
    for (int idx = tid; idx < 128 * 64; idx += 256) {
        int n  = idx >> 6;
        int k4 = (idx & 63) * 4;
        float4 v = (k4 < 128) ? *(const float4*)&wl[n * 128 + k4]
                              : *(const float4*)&wr[n * 128 + (k4 - 128)];
        split4_store(sB_hi, sB_lo, n * P2 + k4, v);
    }
    float2 bias_t[4];
    #pragma unroll
    for (int t = 0; t < 4; t++)
        bias_t[t] = *(const float2*)&bl[n0 + t * 8 + q * 2];
    __syncthreads();

    const int ntiles = (N_NODES + TM - 1) / TM;
    for (int tile = blockIdx.x; tile < ntiles; tile += gridDim.x) {
        const int row0 = tile * TM;
        __syncthreads();
        // stage A tile (32 x 256): [agg | xroot], hi/lo split, float4 path
        #pragma unroll 2
        for (int idx = tid; idx < TM * 64; idx += 256) {
            int r  = idx >> 6;
            int k4 = (idx & 63) * 4;
            int grow = row0 + r;
            float4 v = make_float4(0.f, 0.f, 0.f, 0.f);
            if (grow < N_NODES)
                v = (k4 < 128)
                    ? *(const float4*)&g_agg[(size_t)grow * D + k4]
                    : __ldg((const float4*)&xroot[(size_t)grow * D + (k4 - 128)]);
            split4_store(sA_hi, sA_lo, r * P2 + k4, v);
        }
        __syncthreads();

        float acc[4][4];
        #pragma unroll
        for (int t = 0; t < 4; t++)
            #pragma unroll
            for (int c = 0; c < 4; c++) acc[t][c] = 0.f;

        #pragma unroll 4
        for (int ks = 0; ks < 16; ks++) {
            const int kk = ks * 16 + q * 2;
            const int ra = (mr + g) * P2;
            uint32_t ah0 = *(const uint32_t*)&sA_hi[ra + kk];
            uint32_t ah1 = *(const uint32_t*)&sA_hi[ra + 8 * P2 + kk];
            uint32_t ah2 = *(const uint32_t*)&sA_hi[ra + kk + 8];
            uint32_t ah3 = *(const uint32_t*)&sA_hi[ra + 8 * P2 + kk + 8];
            uint32_t al0 = *(const uint32_t*)&sA_lo[ra + kk];
            uint32_t al1 = *(const uint32_t*)&sA_lo[ra + 8 * P2 + kk];
            uint32_t al2 = *(const uint32_t*)&sA_lo[ra + kk + 8];
            uint32_t al3 = *(const uint32_t*)&sA_lo[ra + 8 * P2 + kk + 8];
            #pragma unroll
            for (int t = 0; t < 4; t++) {
                const int nb = (n0 + t * 8 + g) * P2;
                uint32_t bh0 = *(const uint32_t*)&sB_hi[nb + kk];
                uint32_t bh1 = *(const uint32_t*)&sB_hi[nb + kk + 8];
                uint32_t bl0_ = *(const uint32_t*)&sB_lo[nb + kk];
                uint32_t bl1_ = *(const uint32_t*)&sB_lo[nb + kk + 8];
                MMA_BF16(acc[t], ah0, ah1, ah2, ah3, bh0, bh1);
                MMA_BF16(acc[t], ah0, ah1, ah2, ah3, bl0_, bl1_);
                MMA_BF16(acc[t], al0, al1, al2, al3, bh0, bh1);
            }
        }

        // epilogue: bias + relu, f32 store
        const int rA = row0 + mr + g;
        const int rB = rA + 8;
        #pragma unroll
        for (int t = 0; t < 4; t++) {
            const int col0 = n0 + t * 8 + q * 2;
            if (rA < N_NODES) {
                float2 o;
                o.x = fmaxf(acc[t][0] + bias_t[t].x, 0.f);
                o.y = fmaxf(acc[t][1] + bias_t[t].y, 0.f);
                *(float2*)&out[(size_t)rA * D + col0] = o;
            }
            if (rB < N_NODES) {
                float2 o;
                o.x = fmaxf(acc[t][2] + bias_t[t].x, 0.f);
                o.y = fmaxf(acc[t][3] + bias_t[t].y, 0.f);
                *(float2*)&out[(size_t)rB * D + col0] = o;
            }
        }
    }
}

// ================= fused MLP head (tensor core) =================
// h3 = relu(g_h2 @ mw1^T + mb1);  out = h3 @ mw2^T + mb2   -> [N]
__global__ __launch_bounds__(256, 2)
void k_mlp_mma(const float* __restrict__ mw1, const float* __restrict__ mb1,
               const float* __restrict__ mw2, const float* __restrict__ mb2,
               float* __restrict__ out) {
    extern __shared__ __nv_bfloat16 sm[];
    __nv_bfloat16* sB_hi = sm;                       // 128 * P1
    __nv_bfloat16* sB_lo = sB_hi + 128 * P1;
    __nv_bfloat16* sA_hi = sB_lo + 128 * P1;         // 32 * P1
    __nv_bfloat16* sA_lo = sA_hi + 32 * P1;
    float* s_part = (float*)(sA_lo + 32 * P1);       // [4][32]

    const int tid  = threadIdx.x;
    const int lane = tid & 31;
    const int w    = tid >> 5;
    const int g    = lane >> 2;
    const int q    = lane & 3;
    const int mr   = (w & 1) * 16;
    const int n0   = (w >> 1) * 32;
    const int grp  = w >> 1;

    for (int idx = tid; idx < 128 * 32; idx += 256) {
        int n  = idx >> 5;
        int k4 = (idx & 31) * 4;
        float4 v = *(const float4*)&mw1[n * 128 + k4];
        split4_store(sB_hi, sB_lo, n * P1 + k4, v);
    }
    float2 b1_t[4], w2_t[4];
    #pragma unroll
    for (int t = 0; t < 4; t++) {
        b1_t[t] = *(const float2*)&mb1[n0 + t * 8 + q * 2];
        w2_t[t] = *(const float2*)&mw2[n0 + t * 8 + q * 2];
    }
    const float b2 = mb2[0];
    __syncthreads();

    const int ntiles = (N_NODES + TM - 1) / TM;
    for (int tile = blockIdx.x; tile < ntiles; tile += gridDim.x) {
        const int row0 = tile * TM;
        __syncthreads();
        #pragma unroll 2
        for (int idx = tid; idx < TM * 32; idx += 256) {
            int r  = idx >> 5;
            int k4 = (idx & 31) * 4;
            int grow = row0 + r;
            float4 v = (grow < N_NODES)
                ? *(const float4*)&g_h2[(size_t)grow * D + k4]
                : make_float4(0.f, 0.f, 0.f, 0.f);
            split4_store(sA_hi, sA_lo, r * P1 + k4, v);
        }
        __syncthreads();

        float acc[4][4];
        #pragma unroll
        for (int t = 0; t < 4; t++)
            #pragma unroll
            for (int c = 0; c < 4; c++) acc[t][c] = 0.f;

        #pragma unroll 4
        for (int ks = 0; ks < 8; ks++) {
            const int kk = ks * 16 + q * 2;
            const int ra = (mr + g) * P1;
            uint32_t ah0 = *(const uint32_t*)&sA_hi[ra + kk];
            uint32_t ah1 = *(const uint32_t*)&sA_hi[ra + 8 * P1 + kk];
            uint32_t ah2 = *(const uint32_t*)&sA_hi[ra + kk + 8];
            uint32_t ah3 = *(const uint32_t*)&sA_hi[ra + 8 * P1 + kk + 8];
            uint32_t al0 = *(const uint32_t*)&sA_lo[ra + kk];
            uint32_t al1 = *(const uint32_t*)&sA_lo[ra + 8 * P1 + kk];
            uint32_t al2 = *(const uint32_t*)&sA_lo[ra + kk + 8];
            uint32_t al3 = *(const uint32_t*)&sA_lo[ra + 8 * P1 + kk + 8];
            #pragma unroll
            for (int t = 0; t < 4; t++) {
                const int nb = (n0 + t * 8 + g) * P1;
                uint32_t bh0 = *(const uint32_t*)&sB_hi[nb + kk];
                uint32_t bh1 = *(const uint32_t*)&sB_hi[nb + kk + 8];
                uint32_t bl0_ = *(const uint32_t*)&sB_lo[nb + kk];
                uint32_t bl1_ = *(const uint32_t*)&sB_lo[nb + kk + 8];
                MMA_BF16(acc[t], ah0, ah1, ah2, ah3, bh0, bh1);
                MMA_BF16(acc[t], ah0, ah1, ah2, ah3, bl0_, bl1_);
                MMA_BF16(acc[t], al0, al1, al2, al3, bh0, bh1);
            }
        }

        // head: relu then dot with mw2 over this warp's 32 cols
        float pg = 0.f, pg8 = 0.f;
        #pragma unroll
        for (int t = 0; t < 4; t++) {
            pg  += fmaxf(acc[t][0] + b1_t[t].x, 0.f) * w2_t[t].x
                 + fmaxf(acc[t][1] + b1_t[t].y, 0.f) * w2_t[t].y;
            pg8 += fmaxf(acc[t][2] + b1_t[t].x, 0.f) * w2_t[t].x
                 + fmaxf(acc[t][3] + b1_t[t].y, 0.f) * w2_t[t].y;
        }
        pg  += __shfl_xor_sync(0xffffffffu, pg, 1);
        pg  += __shfl_xor_sync(0xffffffffu, pg, 2);
        pg8 += __shfl_xor_sync(0xffffffffu, pg8, 1);
        pg8 += __shfl_xor_sync(0xffffffffu, pg8, 2);
        if (q == 0) {
            s_part[grp * 32 + mr + g]     = pg;
            s_part[grp * 32 + mr + g + 8] = pg8;
        }
        __syncthreads();
        if (tid < 32) {
            int grow = row0 + tid;
            if (grow < N_NODES) {
                out[grow] = s_part[tid] + s_part[32 + tid] + s_part[64 + tid]
                          + s_part[96 + tid] + b2;
            }
        }
    }
}

extern "C" void kernel_launch(void* const* d_in, const int* in_sizes, int n_in,
                              void* d_out, int out_size) {
    const float* x   = (const float*)d_in[0];
    const int*   ei  = (const int*)d_in[1];      // int32 (JAX x64 disabled)
    const float* w1l = (const float*)d_in[2];
    const float* b1l = (const float*)d_in[3];
    const float* w1r = (const float*)d_in[4];
    const float* w2l = (const float*)d_in[5];
    const float* b2l = (const float*)d_in[6];
    const float* w2r = (const float*)d_in[7];
    const float* mw1 = (const float*)d_in[8];
    const float* mb1 = (const float*)d_in[9];
    const float* mw2 = (const float*)d_in[10];
    const float* mb2 = (const float*)d_in[11];
    float* out = (float*)d_out;
    const int E = in_sizes[1] / 2;

    const int sage_smem = (2 * 128 * P2 + 2 * 32 * P2) * (int)sizeof(__nv_bfloat16); // 168960
    const int mlp_smem  = (2 * 128 * P1 + 2 * 32 * P1) * (int)sizeof(__nv_bfloat16)
                        + 4 * 32 * (int)sizeof(float);                               // 87552
    cudaFuncSetAttribute(k_sage_mma, cudaFuncAttributeMaxDynamicSharedMemorySize, sage_smem);
    cudaFuncSetAttribute(k_mlp_mma,  cudaFuncAttributeMaxDynamicSharedMemorySize, mlp_smem);

    // ---- CSR build ----
    k_zero_cnt<<<(N_NODES + 255) / 256, 256>>>();
    k_count<<<(E + 255) / 256, 256>>>(ei, E);
    k_scan1<<<SCAN_NB, SCAN_BS>>>();
    k_scan2<<<1, 64>>>();
    k_scan3<<<(N_NODES + 255) / 256, 256>>>();
    k_fill<<<(E + 255) / 256, 256>>>(ei, E);

    const int gat_blocks = (N_NODES + 7) / 8;

    // ---- layer 1 ----
    k_gather<<<gat_blocks, 256>>>(x, 0);
    k_sage_mma<<<148, 256, sage_smem>>>(x, w1l, b1l, w1r, 0);

    // ---- layer 2 ----
    k_gather<<<gat_blocks, 256>>>(x, 1);
    k_sage_mma<<<148, 256, sage_smem>>>(x, w2l, b2l, w2r, 1);

    // ---- MLP head ----
    k_mlp_mma<<<296, 256, mlp_smem>>>(mw1, mb1, mw2, mb2, out);
}